// round 16
// baseline (speedup 1.0000x reference)
#include <cuda_runtime.h>

typedef unsigned long long ull;

// Packed weights produced by prep_kernel each launch.
__device__ ull   g_w1p[18];     // fp32x2 pairs: (ch 2p, ch 2p+1), pre-halved s1/2*sign, tap k
__device__ int   g_w2p[36];     // word[oc*9+tap], bytes = int8 sign per ic
__device__ int   g_wfp[490];    // word[o*49 + p], bytes = sign per channel c (j = c*49+p)
__device__ float g_sc[2];       // {s2, 2*sf}

__global__ void prep_kernel(const float* __restrict__ w1,
                            const float* __restrict__ w2,
                            const float* __restrict__ wf) {
    __shared__ float swf[1960];
    __shared__ float redm[16][3];
    __shared__ float sS[3];
    const int tid = threadIdx.x, lane = tid & 31, wid = tid >> 5;

    const float4* wf4 = (const float4*)wf;   // 1960 floats = 490 float4
    float m1 = 0.f, m2 = 0.f, mf = 0.f;
    for (int i = tid; i < 490; i += 512) {
        float4 v = __ldg(wf4 + i);
        swf[4 * i + 0] = v.x; swf[4 * i + 1] = v.y;
        swf[4 * i + 2] = v.z; swf[4 * i + 3] = v.w;
        mf = fmaxf(mf, fmaxf(fmaxf(fabsf(v.x), fabsf(v.y)),
                             fmaxf(fabsf(v.z), fabsf(v.w))));
    }
    if (tid < 36)  m1 = fabsf(__ldg(w1 + tid));
    if (tid < 144) m2 = fabsf(__ldg(w2 + tid));
#pragma unroll
    for (int o = 16; o; o >>= 1) {
        m1 = fmaxf(m1, __shfl_xor_sync(0xffffffffu, m1, o));
        m2 = fmaxf(m2, __shfl_xor_sync(0xffffffffu, m2, o));
        mf = fmaxf(mf, __shfl_xor_sync(0xffffffffu, mf, o));
    }
    if (lane == 0) { redm[wid][0] = m1; redm[wid][1] = m2; redm[wid][2] = mf; }
    __syncthreads();
    if (tid < 3) {
        float a = redm[0][tid];
        for (int w = 1; w < 16; w++) a = fmaxf(a, redm[w][tid]);
        sS[tid] = a;
    }
    __syncthreads();
    const float s1f = sS[0], s2 = sS[1], sf = sS[2];

    if (tid < 18) {
        int k = tid % 9, p = tid / 9;
        float wa = __ldg(w1 + (2 * p) * 9 + k);
        float wb = __ldg(w1 + (2 * p + 1) * 9 + k);
        float qa = fminf(fmaxf(rintf(wa / s1f), -1.f), 1.f) * s1f * 0.5f;  // pre-halved, exact
        float qb = fminf(fmaxf(rintf(wb / s1f), -1.f), 1.f) * s1f * 0.5f;
        ull lo = __float_as_uint(qa);
        ull hi = __float_as_uint(qb);
        g_w1p[tid] = lo | (hi << 32);
    }
    if (tid >= 64 && tid < 100) {
        int t = tid - 64;
        int oc = t / 9, tap = t % 9;
        int word = 0;
        for (int ic = 0; ic < 4; ic++) {
            float w = __ldg(w2 + (oc * 4 + ic) * 9 + tap);
            int si = (int)rintf(w / s2);
            si = min(1, max(-1, si));
            word |= (si & 0xFF) << (8 * ic);
        }
        g_w2p[t] = word;
    }
    for (int g = tid; g < 490; g += 512) {
        int o = g / 49, p = g % 49;
        int word = 0;
        for (int c = 0; c < 4; c++) {
            float w = swf[o * 196 + c * 49 + p];
            int si = (int)rintf(w / sf);
            si = min(1, max(-1, si));
            word |= (si & 0xFF) << (8 * c);
        }
        g_wfp[g] = word;
    }
    if (tid == 0) { g_sc[0] = s2; g_sc[1] = 2.f * sf; }
}

__device__ __forceinline__ ull pk2(float v) {
    ull d; asm("mov.b64 %0, {%1, %1};" : "=l"(d) : "f"(v)); return d;
}
__device__ __forceinline__ ull fma2(ull a, ull b, ull c) {
    ull d; asm("fma.rn.f32x2 %0, %1, %2, %3;" : "=l"(d) : "l"(a), "l"(b), "l"(c)); return d;
}
__device__ __forceinline__ float lo2(ull v) { return __uint_as_float((unsigned)v); }
__device__ __forceinline__ float hi2(ull v) { return __uint_as_float((unsigned)(v >> 32)); }

// level = rint(v) saturated below at 0 (top clamp done packed via vminu4)
__device__ __forceinline__ int qlev(float v) {
    unsigned r; asm("cvt.rni.sat.u32.f32 %0, %1;" : "=r"(r) : "f"(v));
    return (int)r;
}
__device__ __forceinline__ int pack4(int a, int b, int c, int d) {
    int ab, cd, r;
    asm("prmt.b32 %0, %1, %2, 0x0040;" : "=r"(ab) : "r"(a), "r"(b));
    asm("prmt.b32 %0, %1, %2, 0x0040;" : "=r"(cd) : "r"(c), "r"(d));
    asm("prmt.b32 %0, %1, %2, 0x5410;" : "=r"(r) : "r"(ab), "r"(cd));
    return r;
}

__global__ __launch_bounds__(256, 4)
void net_warp(const float* __restrict__ x, float* __restrict__ out) {
    __shared__ ull   sw1p[18];
    __shared__ int   sw2s[36];
    __shared__ int   swfs[497];   // 490 weights + 7 zero pad for FC split
    __shared__ float sscs[2];

    const int tid  = threadIdx.x;
    const int lane = tid & 31;
    const int wid  = tid >> 5;

    const int  img = blockIdx.x * 8 + wid;
    const bool isA = lane < 16;
    const int  lx  = lane & 15;

    // ---- input prefetch first: overlap with weight-staging L2 reads ----
    const bool   colOK = lane < 28;
    const float* xcol  = x + (size_t)img * 784 + lane;
    float buf[4];
#pragma unroll
    for (int i = 0; i < 4; i++) buf[i] = colOK ? __ldg(xcol + i * 28) : 0.f;

    // stage packed weights (L2-resident globals)
    if (tid < 18) sw1p[tid] = g_w1p[tid];
    if (tid < 36) sw2s[tid] = g_w2p[tid];
    for (int i = tid; i < 490; i += 256) swfs[i] = g_wfp[i];
    if (tid >= 64 && tid < 71) swfs[490 + (tid - 64)] = 0;
    if (tid < 2) sscs[tid] = g_sc[tid];
    __syncthreads();

    ull w01[9], w23[9];
#pragma unroll
    for (int k = 0; k < 9; k++) { w01[k] = sw1p[k]; w23[k] = sw1p[9 + k]; }
    const float s2  = sscs[0];
    const float osc = sscs[1];

    // Sparsity of 2-bit-quantized conv1 weights: most taps are exactly +0.0
    // (value = q*s1/2 with q=0). Per channel-pair, per ky row, test the 3-tap
    // group; the test is warp-uniform (same weights everywhere) -> no divergence.
    // Skipping fma2 with multiplier +0.0 is bit-exact for finite inputs.
    const bool nzA0 = ((w01[0] | w01[1] | w01[2]) != 0ull);
    const bool nzA1 = ((w01[3] | w01[4] | w01[5]) != 0ull);
    const bool nzA2 = ((w01[6] | w01[7] | w01[8]) != 0ull);
    const bool nzB0 = ((w23[0] | w23[1] | w23[2]) != 0ull);
    const bool nzB1 = ((w23[3] | w23[4] | w23[5]) != 0ull);
    const bool nzB2 = ((w23[6] | w23[7] | w23[8]) != 0ull);

    // Redistribution source: lane lx receives pooled COLUMN lx-1 (lanes 0 and 15
    // receive the zero pad, sourced from provably-zero lane 31).
    int srcp = 2 * lx - 2;
    if (srcp < 0 || srcp > 26) srcp = 31;
    // left-neighbor source for conv1: lane-1, with lane0 -> lane31 (zero)
    const int lfidx = (lane + 31) & 31;

    // ---- conv1 (FFMA2, rows streamed) + pool1 + quant + split-redistribution ----
    ull a01[3], a23[3];
    int arr[10];
#pragma unroll
    for (int i = 0; i < 10; i++) arr[i] = 0;

#define C1_POOL2(y)                                                            \
    {                                                                          \
        const int se = (y) % 3, so = ((y) + 1) % 3;                            \
        float v0 = fmaxf(lo2(a01[se]), lo2(a01[so]));                          \
        float v1 = fmaxf(hi2(a01[se]), hi2(a01[so]));                          \
        float v2 = fmaxf(lo2(a23[se]), lo2(a23[so]));                          \
        float v3 = fmaxf(hi2(a23[se]), hi2(a23[so]));                          \
        int l0 = qlev(v0);                                                     \
        int l1 = qlev(v1);                                                     \
        int l2 = qlev(v2);                                                     \
        int l3 = qlev(v3);                                                     \
        int word = pack4(l0, l1, l2, l3);                                      \
        word = __vmaxu4(word, __shfl_down_sync(0xffffffffu, word, 1));         \
        word = __vminu4(word, 0x03030303);                                     \
        int rv = __shfl_sync(0xffffffffu, word, srcp);                         \
        const int t_ = (y) >> 1;                                               \
        if (t_ <= 8 && isA)  arr[t_ + 1] = rv;                                 \
        if (t_ >= 7 && !isA) arr[t_ - 7] = rv;                                 \
    }

#pragma unroll
    for (int r = 0; r < 28; r++) {
        float mv = buf[r & 3];
        if (r + 4 < 28) buf[r & 3] = colOK ? __ldg(xcol + (r + 4) * 28) : 0.f;
        float lf = __shfl_sync(0xffffffffu, mv, lfidx);    // lane0 <- lane31 = 0
        float rt = __shfl_down_sync(0xffffffffu, mv, 1);   // lane27 reads lane28 = 0; lane31 keeps 0
        ull pl = pk2(lf), pm = pk2(mv), pr = pk2(rt);

        // ky=2: completes output row r-1 (slot (r-1)%3)
        if (r >= 1) {
            const int s = (r - 1) % 3;
            if (nzA2) {
                ull c01 = a01[s];
                c01 = fma2(w01[6], pl, c01);
                c01 = fma2(w01[7], pm, c01);
                c01 = fma2(w01[8], pr, c01);
                a01[s] = c01;
            }
            if (nzB2) {
                ull c23 = a23[s];
                c23 = fma2(w23[6], pl, c23);
                c23 = fma2(w23[7], pm, c23);
                c23 = fma2(w23[8], pr, c23);
                a23[s] = c23;
            }
        }
        // ky=1: output row r (fresh at r==0)
        {
            const int s = r % 3;
            ull c01 = (r == 0) ? 0ull : a01[s];
            ull c23 = (r == 0) ? 0ull : a23[s];
            if (nzA1) {
                c01 = fma2(w01[3], pl, c01);
                c01 = fma2(w01[4], pm, c01);
                c01 = fma2(w01[5], pr, c01);
            }
            if (nzB1) {
                c23 = fma2(w23[3], pl, c23);
                c23 = fma2(w23[4], pm, c23);
                c23 = fma2(w23[5], pr, c23);
            }
            a01[s] = c01; a23[s] = c23;
        }
        // pool pair (r-2, r-1): slots intact (fresh write below)
        if (r >= 2 && (r & 1) == 0) C1_POOL2(r - 2);
        // ky=0: fresh output row r+1 (slot recycled after the pool)
        if (r <= 26) {
            const int s = (r + 1) % 3;
            ull c01 = 0ull, c23 = 0ull;
            if (nzA0) {
                c01 = fma2(w01[0], pl, 0ull);
                c01 = fma2(w01[1], pm, c01);
                c01 = fma2(w01[2], pr, c01);
            }
            if (nzB0) {
                c23 = fma2(w23[0], pl, 0ull);
                c23 = fma2(w23[1], pm, c23);
                c23 = fma2(w23[2], pr, c23);
            }
            a01[s] = c01; a23[s] = c23;
        }
    }
    C1_POOL2(26);   // final pair (26, 27)

    // ---- conv2 (dp4a, padded stream, half-warp row split) + pool2 ----
    int w2r[36];
#pragma unroll
    for (int k = 0; k < 36; k++) w2r[k] = sw2s[k];

    int b0[3], b1[3], b2[3], b3[3];
    int flat[4];   // A: qy 0..3; B: qy 4..6 at flat[0..2] (flat[3] garbage, zero-weighted)

#define C2_ACC(jj, s, fresh)                                                   \
    {                                                                          \
        int c0 = (fresh) ? 0 : b0[s];                                          \
        int c1 = (fresh) ? 0 : b1[s];                                          \
        int c2 = (fresh) ? 0 : b2[s];                                          \
        int c3 = (fresh) ? 0 : b3[s];                                          \
        c0 = __dp4a(lL, w2r[0 * 9 + (jj) * 3 + 0], c0);                        \
        c0 = __dp4a(lv, w2r[0 * 9 + (jj) * 3 + 1], c0);                        \
        c0 = __dp4a(lR, w2r[0 * 9 + (jj) * 3 + 2], c0);                        \
        c1 = __dp4a(lL, w2r[1 * 9 + (jj) * 3 + 0], c1);                        \
        c1 = __dp4a(lv, w2r[1 * 9 + (jj) * 3 + 1], c1);                        \
        c1 = __dp4a(lR, w2r[1 * 9 + (jj) * 3 + 2], c1);                        \
        c2 = __dp4a(lL, w2r[2 * 9 + (jj) * 3 + 0], c2);                        \
        c2 = __dp4a(lv, w2r[2 * 9 + (jj) * 3 + 1], c2);                        \
        c2 = __dp4a(lR, w2r[2 * 9 + (jj) * 3 + 2], c2);                        \
        c3 = __dp4a(lL, w2r[3 * 9 + (jj) * 3 + 0], c3);                        \
        c3 = __dp4a(lv, w2r[3 * 9 + (jj) * 3 + 1], c3);                        \
        c3 = __dp4a(lR, w2r[3 * 9 + (jj) * 3 + 2], c3);                        \
        b0[s] = c0; b1[s] = c1; b2[s] = c2; b3[s] = c3;                        \
    }

#define C2_POOL2(j)                                                            \
    {                                                                          \
        const int se = (j) % 3, so = ((j) + 1) % 3;                            \
        int m0 = max(b0[se], b0[so]);                                          \
        int m1 = max(b1[se], b1[so]);                                          \
        int m2 = max(b2[se], b2[so]);                                          \
        int m3 = max(b3[se], b3[so]);                                          \
        int l0 = qlev(s2 * (float)m0);                                         \
        int l1 = qlev(s2 * (float)m1);                                         \
        int l2 = qlev(s2 * (float)m2);                                         \
        int l3 = qlev(s2 * (float)m3);                                         \
        int word = pack4(l0, l1, l2, l3);                                      \
        word = __vmaxu4(word, __shfl_down_sync(0xffffffffu, word, 1));         \
        word = __vminu4(word, 0x03030303);                                     \
        flat[(j) >> 1] = word;   /* valid at odd lanes 2qx+1 per half */       \
    }

#pragma unroll
    for (int k = 0; k <= 9; k++) {
        int lv = arr[k];
        int lL = __shfl_up_sync(0xffffffffu, lv, 1);     // lane0 own=0; lane16 reads lane15=0
        int lR = __shfl_down_sync(0xffffffffu, lv, 1);   // lane14 reads lane15=0; lane30 reads lane31=0
        if (k >= 2) C2_ACC(2, (k - 2) % 3, false)        // completes j = k-2
        if (k >= 1 && k <= 8) C2_ACC(1, (k - 1) % 3, false)
        if (k >= 3 && (k & 1)) C2_POOL2(k - 3)           // pairs (0,1),(2,3),(4,5),(6,7)
        if (k <= 7) C2_ACC(0, k % 3, true)               // fresh j = k
    }

    // ---- FC, split across half-warps: A qy0..3 (28 items), B qy4..6 (21 + 7 zero-pad) ----
    const int o = min(lx, 9);
    const int laneBase = o * 49 + (isA ? 0 : 28);
    const int grp = lane & 16;
    int facc = 0;
#pragma unroll
    for (int i = 0; i < 21; i++) {
        int word = __shfl_sync(0xffffffffu, flat[i / 7], grp + 2 * (i % 7) + 1);
        facc = __dp4a(word, swfs[laneBase + i], facc);
    }
    const int base2 = isA ? laneBase : 469;    // B tail (i=21..27) hits zero pad 490..496
#pragma unroll
    for (int i = 21; i < 28; i++) {
        int word = __shfl_sync(0xffffffffu, flat[3], grp + 2 * (i - 21) + 1);
        facc = __dp4a(word, swfs[base2 + i], facc);
    }
    int bpart = __shfl_sync(0xffffffffu, facc, 16 + lx);
    if (lane < 10)
        out[(size_t)img * 10 + lane] = osc * (float)(facc + bpart);
}

extern "C" void kernel_launch(void* const* d_in, const int* in_sizes, int n_in,
                              void* d_out, int out_size) {
    const float* x  = (const float*)d_in[0];
    const float* w1 = (const float*)d_in[1];
    const float* w2 = (const float*)d_in[2];
    const float* wf = (const float*)d_in[3];
    float* out = (float*)d_out;

    prep_kernel<<<1, 512>>>(w1, w2, wf);

    int B = in_sizes[0] / 784;          // 32768 images, 8 warps/block = 1 image/warp
    net_warp<<<B / 8, 256>>>(x, out);
}

// round 17
// speedup vs baseline: 1.4248x; 1.4248x over previous
#include <cuda_runtime.h>

typedef unsigned long long ull;

// Packed weights produced by prep_kernel each launch.
__device__ ull   g_w1p[18];     // fp32x2 pairs: (ch 2p, ch 2p+1), pre-halved s1/2*sign, tap k
__device__ int   g_w2p[36];     // word[oc*9+tap], bytes = int8 sign per ic
__device__ int   g_wfp[490];    // word[o*49 + p], bytes = sign per channel c (j = c*49+p)
__device__ float g_sc[2];       // {s2, 2*sf}

__global__ void prep_kernel(const float* __restrict__ w1,
                            const float* __restrict__ w2,
                            const float* __restrict__ wf) {
    __shared__ float swf[1960];
    __shared__ float redm[16][3];
    __shared__ float sS[3];
    const int tid = threadIdx.x, lane = tid & 31, wid = tid >> 5;

    const float4* wf4 = (const float4*)wf;   // 1960 floats = 490 float4
    float m1 = 0.f, m2 = 0.f, mf = 0.f;
    for (int i = tid; i < 490; i += 512) {
        float4 v = __ldg(wf4 + i);
        swf[4 * i + 0] = v.x; swf[4 * i + 1] = v.y;
        swf[4 * i + 2] = v.z; swf[4 * i + 3] = v.w;
        mf = fmaxf(mf, fmaxf(fmaxf(fabsf(v.x), fabsf(v.y)),
                             fmaxf(fabsf(v.z), fabsf(v.w))));
    }
    if (tid < 36)  m1 = fabsf(__ldg(w1 + tid));
    if (tid < 144) m2 = fabsf(__ldg(w2 + tid));
#pragma unroll
    for (int o = 16; o; o >>= 1) {
        m1 = fmaxf(m1, __shfl_xor_sync(0xffffffffu, m1, o));
        m2 = fmaxf(m2, __shfl_xor_sync(0xffffffffu, m2, o));
        mf = fmaxf(mf, __shfl_xor_sync(0xffffffffu, mf, o));
    }
    if (lane == 0) { redm[wid][0] = m1; redm[wid][1] = m2; redm[wid][2] = mf; }
    __syncthreads();
    if (tid < 3) {
        float a = redm[0][tid];
        for (int w = 1; w < 16; w++) a = fmaxf(a, redm[w][tid]);
        sS[tid] = a;
    }
    __syncthreads();
    const float s1f = sS[0], s2 = sS[1], sf = sS[2];

    if (tid < 18) {
        int k = tid % 9, p = tid / 9;
        float wa = __ldg(w1 + (2 * p) * 9 + k);
        float wb = __ldg(w1 + (2 * p + 1) * 9 + k);
        float qa = fminf(fmaxf(rintf(wa / s1f), -1.f), 1.f) * s1f * 0.5f;  // pre-halved, exact
        float qb = fminf(fmaxf(rintf(wb / s1f), -1.f), 1.f) * s1f * 0.5f;
        ull lo = __float_as_uint(qa);
        ull hi = __float_as_uint(qb);
        g_w1p[tid] = lo | (hi << 32);
    }
    if (tid >= 64 && tid < 100) {
        int t = tid - 64;
        int oc = t / 9, tap = t % 9;
        int word = 0;
        for (int ic = 0; ic < 4; ic++) {
            float w = __ldg(w2 + (oc * 4 + ic) * 9 + tap);
            int si = (int)rintf(w / s2);
            si = min(1, max(-1, si));
            word |= (si & 0xFF) << (8 * ic);
        }
        g_w2p[t] = word;
    }
    for (int g = tid; g < 490; g += 512) {
        int o = g / 49, p = g % 49;
        int word = 0;
        for (int c = 0; c < 4; c++) {
            float w = swf[o * 196 + c * 49 + p];
            int si = (int)rintf(w / sf);
            si = min(1, max(-1, si));
            word |= (si & 0xFF) << (8 * c);
        }
        g_wfp[g] = word;
    }
    if (tid == 0) { g_sc[0] = s2; g_sc[1] = 2.f * sf; }
}

__device__ __forceinline__ ull pk2(float v) {
    ull d; asm("mov.b64 %0, {%1, %1};" : "=l"(d) : "f"(v)); return d;
}
__device__ __forceinline__ ull fma2(ull a, ull b, ull c) {
    ull d; asm("fma.rn.f32x2 %0, %1, %2, %3;" : "=l"(d) : "l"(a), "l"(b), "l"(c)); return d;
}
__device__ __forceinline__ float lo2(ull v) { return __uint_as_float((unsigned)v); }
__device__ __forceinline__ float hi2(ull v) { return __uint_as_float((unsigned)(v >> 32)); }

// level = rint(v) saturated below at 0 (top clamp done packed via vminu4)
__device__ __forceinline__ int qlev(float v) {
    unsigned r; asm("cvt.rni.sat.u32.f32 %0, %1;" : "=r"(r) : "f"(v));
    return (int)r;
}
__device__ __forceinline__ int pack4(int a, int b, int c, int d) {
    int ab, cd, r;
    asm("prmt.b32 %0, %1, %2, 0x0040;" : "=r"(ab) : "r"(a), "r"(b));
    asm("prmt.b32 %0, %1, %2, 0x0040;" : "=r"(cd) : "r"(c), "r"(d));
    asm("prmt.b32 %0, %1, %2, 0x5410;" : "=r"(r) : "r"(ab), "r"(cd));
    return r;
}

__global__ __launch_bounds__(256, 4)
void net_warp(const float* __restrict__ x, float* __restrict__ out) {
    __shared__ ull   sw1p[18];
    __shared__ int   sw2s[36];
    __shared__ int   swfs[497];   // 490 weights + 7 zero pad for FC split
    __shared__ float sscs[2];

    const int tid  = threadIdx.x;
    const int lane = tid & 31;
    const int wid  = tid >> 5;

    const int  img = blockIdx.x * 8 + wid;
    const bool isA = lane < 16;
    const int  lx  = lane & 15;

    // ---- input prefetch first: overlap with weight-staging L2 reads ----
    const bool   colOK = lane < 28;
    const float* xcol  = x + (size_t)img * 784 + lane;
    float buf[4];
#pragma unroll
    for (int i = 0; i < 4; i++) buf[i] = colOK ? __ldg(xcol + i * 28) : 0.f;

    // stage packed weights (L2-resident globals)
    if (tid < 18) sw1p[tid] = g_w1p[tid];
    if (tid < 36) sw2s[tid] = g_w2p[tid];
    for (int i = tid; i < 490; i += 256) swfs[i] = g_wfp[i];
    if (tid >= 64 && tid < 71) swfs[490 + (tid - 64)] = 0;
    if (tid < 2) sscs[tid] = g_sc[tid];
    __syncthreads();

    ull w01[9], w23[9];
#pragma unroll
    for (int k = 0; k < 9; k++) { w01[k] = sw1p[k]; w23[k] = sw1p[9 + k]; }
    const float s2  = sscs[0];
    const float osc = sscs[1];

    // Redistribution source: lane lx receives pooled COLUMN lx-1 (lanes 0 and 15
    // receive the zero pad, sourced from provably-zero lane 31).
    int srcp = 2 * lx - 2;
    if (srcp < 0 || srcp > 26) srcp = 31;
    // left-neighbor source for conv1: lane-1, with lane0 -> lane31 (zero)
    const int lfidx = (lane + 31) & 31;

    // ---- conv1 (FFMA2, rows streamed) + pool1 + quant + split-redistribution ----
    // Per-iteration order: ky=2 (completes row r-1), ky=1, POOL pair on even r,
    // ky=0 (fresh row r+1). Pool reads its slots before the fresh write recycles
    // them -> no accumulator copies. Straight-line, branch-free (R16 lesson:
    // runtime-guarded skips cost more in BSSY/BSYNC than the saved fma2s).
    ull a01[3], a23[3];
    int arr[10];
#pragma unroll
    for (int i = 0; i < 10; i++) arr[i] = 0;

#define C1_POOL2(y)                                                            \
    {                                                                          \
        const int se = (y) % 3, so = ((y) + 1) % 3;                            \
        float v0 = fmaxf(lo2(a01[se]), lo2(a01[so]));                          \
        float v1 = fmaxf(hi2(a01[se]), hi2(a01[so]));                          \
        float v2 = fmaxf(lo2(a23[se]), lo2(a23[so]));                          \
        float v3 = fmaxf(hi2(a23[se]), hi2(a23[so]));                          \
        int l0 = qlev(v0);                                                     \
        int l1 = qlev(v1);                                                     \
        int l2 = qlev(v2);                                                     \
        int l3 = qlev(v3);                                                     \
        int word = pack4(l0, l1, l2, l3);                                      \
        word = __vmaxu4(word, __shfl_down_sync(0xffffffffu, word, 1));         \
        word = __vminu4(word, 0x03030303);                                     \
        int rv = __shfl_sync(0xffffffffu, word, srcp);                         \
        const int t_ = (y) >> 1;                                               \
        if (t_ <= 8 && isA)  arr[t_ + 1] = rv;                                 \
        if (t_ >= 7 && !isA) arr[t_ - 7] = rv;                                 \
    }

#pragma unroll
    for (int r = 0; r < 28; r++) {
        float mv = buf[r & 3];
        if (r + 4 < 28) buf[r & 3] = colOK ? __ldg(xcol + (r + 4) * 28) : 0.f;
        float lf = __shfl_sync(0xffffffffu, mv, lfidx);    // lane0 <- lane31 = 0
        float rt = __shfl_down_sync(0xffffffffu, mv, 1);   // lane27 reads lane28 = 0; lane31 keeps 0
        ull pl = pk2(lf), pm = pk2(mv), pr = pk2(rt);

        // ky=2: completes output row r-1 (slot (r-1)%3)
        if (r >= 1) {
            const int s = (r - 1) % 3;
            ull c01 = a01[s], c23 = a23[s];
            c01 = fma2(w01[6], pl, c01);
            c01 = fma2(w01[7], pm, c01);
            c01 = fma2(w01[8], pr, c01);
            c23 = fma2(w23[6], pl, c23);
            c23 = fma2(w23[7], pm, c23);
            c23 = fma2(w23[8], pr, c23);
            a01[s] = c01; a23[s] = c23;
        }
        // ky=1: output row r (fresh only at r==0)
        {
            const int s = r % 3;
            ull c01 = (r == 0) ? 0ull : a01[s];
            ull c23 = (r == 0) ? 0ull : a23[s];
            c01 = fma2(w01[3], pl, c01);
            c01 = fma2(w01[4], pm, c01);
            c01 = fma2(w01[5], pr, c01);
            c23 = fma2(w23[3], pl, c23);
            c23 = fma2(w23[4], pm, c23);
            c23 = fma2(w23[5], pr, c23);
            a01[s] = c01; a23[s] = c23;
        }
        // pool pair (r-2, r-1): slots still intact (fresh write happens below)
        if (r >= 2 && (r & 1) == 0) C1_POOL2(r - 2);
        // ky=0: fresh output row r+1 (slot (r+1)%3 == (r-2)%3, recycled)
        if (r <= 26) {
            const int s = (r + 1) % 3;
            ull c01 = fma2(w01[0], pl, 0ull);
            c01 = fma2(w01[1], pm, c01);
            c01 = fma2(w01[2], pr, c01);
            ull c23 = fma2(w23[0], pl, 0ull);
            c23 = fma2(w23[1], pm, c23);
            c23 = fma2(w23[2], pr, c23);
            a01[s] = c01; a23[s] = c23;
        }
    }
    C1_POOL2(26);   // final pair (26, 27)

    // ---- conv2 (dp4a, padded stream, half-warp row split) + pool2 ----
    int w2r[36];
#pragma unroll
    for (int k = 0; k < 36; k++) w2r[k] = sw2s[k];

    int b0[3], b1[3], b2[3], b3[3];
    int flat[4];   // A: qy 0..3; B: qy 4..6 at flat[0..2] (flat[3] garbage, zero-weighted)

#define C2_ACC(jj, s, fresh)                                                   \
    {                                                                          \
        int c0 = (fresh) ? 0 : b0[s];                                          \
        int c1 = (fresh) ? 0 : b1[s];                                          \
        int c2 = (fresh) ? 0 : b2[s];                                          \
        int c3 = (fresh) ? 0 : b3[s];                                          \
        c0 = __dp4a(lL, w2r[0 * 9 + (jj) * 3 + 0], c0);                        \
        c0 = __dp4a(lv, w2r[0 * 9 + (jj) * 3 + 1], c0);                        \
        c0 = __dp4a(lR, w2r[0 * 9 + (jj) * 3 + 2], c0);                        \
        c1 = __dp4a(lL, w2r[1 * 9 + (jj) * 3 + 0], c1);                        \
        c1 = __dp4a(lv, w2r[1 * 9 + (jj) * 3 + 1], c1);                        \
        c1 = __dp4a(lR, w2r[1 * 9 + (jj) * 3 + 2], c1);                        \
        c2 = __dp4a(lL, w2r[2 * 9 + (jj) * 3 + 0], c2);                        \
        c2 = __dp4a(lv, w2r[2 * 9 + (jj) * 3 + 1], c2);                        \
        c2 = __dp4a(lR, w2r[2 * 9 + (jj) * 3 + 2], c2);                        \
        c3 = __dp4a(lL, w2r[3 * 9 + (jj) * 3 + 0], c3);                        \
        c3 = __dp4a(lv, w2r[3 * 9 + (jj) * 3 + 1], c3);                        \
        c3 = __dp4a(lR, w2r[3 * 9 + (jj) * 3 + 2], c3);                        \
        b0[s] = c0; b1[s] = c1; b2[s] = c2; b3[s] = c3;                        \
    }

#define C2_POOL2(j)                                                            \
    {                                                                          \
        const int se = (j) % 3, so = ((j) + 1) % 3;                            \
        int m0 = max(b0[se], b0[so]);                                          \
        int m1 = max(b1[se], b1[so]);                                          \
        int m2 = max(b2[se], b2[so]);                                          \
        int m3 = max(b3[se], b3[so]);                                          \
        int l0 = qlev(s2 * (float)m0);                                         \
        int l1 = qlev(s2 * (float)m1);                                         \
        int l2 = qlev(s2 * (float)m2);                                         \
        int l3 = qlev(s2 * (float)m3);                                         \
        int word = pack4(l0, l1, l2, l3);                                      \
        word = __vmaxu4(word, __shfl_down_sync(0xffffffffu, word, 1));         \
        word = __vminu4(word, 0x03030303);                                     \
        flat[(j) >> 1] = word;   /* valid at odd lanes 2qx+1 per half */       \
    }

#pragma unroll
    for (int k = 0; k <= 9; k++) {
        int lv = arr[k];
        int lL = __shfl_up_sync(0xffffffffu, lv, 1);     // lane0 own=0; lane16 reads lane15=0
        int lR = __shfl_down_sync(0xffffffffu, lv, 1);   // lane14 reads lane15=0; lane30 reads lane31=0
        if (k >= 2) C2_ACC(2, (k - 2) % 3, false)        // completes j = k-2
        if (k >= 1 && k <= 8) C2_ACC(1, (k - 1) % 3, false)
        if (k >= 3 && (k & 1)) C2_POOL2(k - 3)           // pairs (0,1),(2,3),(4,5),(6,7)
        if (k <= 7) C2_ACC(0, k % 3, true)               // fresh j = k
    }

    // ---- FC, split across half-warps: A qy0..3 (28 items), B qy4..6 (21 + 7 zero-pad) ----
    const int o = min(lx, 9);
    const int laneBase = o * 49 + (isA ? 0 : 28);
    const int grp = lane & 16;
    int facc = 0;
#pragma unroll
    for (int i = 0; i < 21; i++) {
        int word = __shfl_sync(0xffffffffu, flat[i / 7], grp + 2 * (i % 7) + 1);
        facc = __dp4a(word, swfs[laneBase + i], facc);
    }
    const int base2 = isA ? laneBase : 469;    // B tail (i=21..27) hits zero pad 490..496
#pragma unroll
    for (int i = 21; i < 28; i++) {
        int word = __shfl_sync(0xffffffffu, flat[3], grp + 2 * (i - 21) + 1);
        facc = __dp4a(word, swfs[base2 + i], facc);
    }
    int bpart = __shfl_sync(0xffffffffu, facc, 16 + lx);
    if (lane < 10)
        out[(size_t)img * 10 + lane] = osc * (float)(facc + bpart);
}

extern "C" void kernel_launch(void* const* d_in, const int* in_sizes, int n_in,
                              void* d_out, int out_size) {
    const float* x  = (const float*)d_in[0];
    const float* w1 = (const float*)d_in[1];
    const float* w2 = (const float*)d_in[2];
    const float* wf = (const float*)d_in[3];
    float* out = (float*)d_out;

    prep_kernel<<<1, 512>>>(w1, w2, wf);

    int B = in_sizes[0] / 784;          // 32768 images, 8 warps/block = 1 image/warp
    net_warp<<<B / 8, 256>>>(x, out);
}